// round 3
// baseline (speedup 1.0000x reference)
#include <cuda_runtime.h>
#include <math.h>

#define D_MODEL 2048
#define NH      16
#define NKV     4
#define DH      128
#define D1      64
#define D2      64
#define T_SEQ   2048
#define B_SZ    2
#define BT      (B_SZ * T_SEQ)          // 4096
#define WSIZE   1024
#define QKV_N   ((NH + NKV) * DH)       // 2560

// ---------------- scratch (device globals; no runtime allocation) ----------------
__device__ float g_qkv [BT * QKV_N];                 // raw x@W_qkv      (~40 MB)
__device__ float g_rkb [BT * D2];                    // raw x@W_rk + b   (~1 MB)
__device__ float g_gmat[BT * D_MODEL];               // raw x@W_g        (~32 MB)
__device__ float g_Q   [B_SZ * NH  * T_SEQ * DH];    // scaled+roped Q   (~32 MB)
__device__ float g_K   [B_SZ * NKV * T_SEQ * DH];    // tied K (rope in 64..127)
__device__ float g_V   [B_SZ * NKV * T_SEQ * DH];    // tied V
__device__ float g_Y   [B_SZ * NH  * T_SEQ * DH];    // attention output

// ---------------- 128x128x16 fp32 SGEMM, 256 threads, 8x8 microtile ----------------
__global__ void gemm128(const float* __restrict__ A, const float* __restrict__ B,
                        float* __restrict__ C, int N, int K) {
    __shared__ float As[16][132];   // [k][m], padded
    __shared__ float Bs[16][132];   // [k][n], padded
    const int tid = threadIdx.x;
    const int m0 = blockIdx.y << 7, n0 = blockIdx.x << 7;
    const int tx = tid & 15, ty = tid >> 4;
    float acc[8][8];
    #pragma unroll
    for (int i = 0; i < 8; i++)
        #pragma unroll
        for (int j = 0; j < 8; j++) acc[i][j] = 0.f;

    const float* Ab = A + (size_t)m0 * K;
    const float* Bb = B + n0;

    for (int k0 = 0; k0 < K; k0 += 16) {
        #pragma unroll
        for (int i = 0; i < 2; i++) {           // A tile: 128 x 16
            int lin = tid + (i << 8);
            int r = lin >> 2, cg = lin & 3;
            float4 v = *(const float4*)(Ab + (size_t)r * K + k0 + (cg << 2));
            As[(cg << 2) + 0][r] = v.x; As[(cg << 2) + 1][r] = v.y;
            As[(cg << 2) + 2][r] = v.z; As[(cg << 2) + 3][r] = v.w;
        }
        #pragma unroll
        for (int i = 0; i < 2; i++) {           // B tile: 16 x 128
            int lin = tid + (i << 8);
            int r = lin >> 5, cg = lin & 31;
            float4 v = *(const float4*)(Bb + (size_t)(k0 + r) * N + (cg << 2));
            *(float4*)&Bs[r][cg << 2] = v;
        }
        __syncthreads();
        #pragma unroll
        for (int kk = 0; kk < 16; kk++) {
            float a[8], b[8];
            *(float4*)&a[0] = *(const float4*)&As[kk][ty << 3];
            *(float4*)&a[4] = *(const float4*)&As[kk][(ty << 3) + 4];
            *(float4*)&b[0] = *(const float4*)&Bs[kk][tx << 3];
            *(float4*)&b[4] = *(const float4*)&Bs[kk][(tx << 3) + 4];
            #pragma unroll
            for (int i = 0; i < 8; i++)
                #pragma unroll
                for (int j = 0; j < 8; j++) acc[i][j] += a[i] * b[j];
        }
        __syncthreads();
    }
    #pragma unroll
    for (int i = 0; i < 8; i++) {
        float* Cr = C + (size_t)(m0 + (ty << 3) + i) * N + n0 + (tx << 3);
        *(float4*)Cr       = *(float4*)&acc[i][0];
        *(float4*)(Cr + 4) = *(float4*)&acc[i][4];
    }
}

// ---------------- x @ W_rk + b_rk (N=64) ----------------
__global__ void rk_kernel(const float* __restrict__ X, const float* __restrict__ Wrk,
                          const float* __restrict__ brk) {
    const int tok0 = blockIdx.x << 2;        // 4 tokens per block
    __shared__ float xs[4][D_MODEL];
    for (int i = threadIdx.x; i < 4 * D_MODEL / 4; i += 256) {
        int tk = i >> 9, cc = i & 511;
        ((float4*)xs[tk])[cc] = ((const float4*)(X + (size_t)(tok0 + tk) * D_MODEL))[cc];
    }
    __syncthreads();
    const int tk = threadIdx.x >> 6, n = threadIdx.x & 63;
    float acc = brk[n];
    for (int k = 0; k < D_MODEL; k++) acc += xs[tk][k] * Wrk[k * 64 + n];
    g_rkb[(size_t)(tok0 + tk) * D2 + n] = acc;
}

// ---------------- rmsnorm + rope + scaling + KV scatter ----------------
__device__ __forceinline__ float inv_freq_f(int i) {
    // 1/10000^(2i/64) = exp(-i * ln(10000)/32)
    return expf(-(float)i * 0.28782313662425575f);
}

__global__ void prep_kernel(const float* __restrict__ scaler) {
    const int blk = blockIdx.x;              // token index in [0, BT)
    const int b = blk / T_SEQ, t = blk % T_SEQ;
    const int w = threadIdx.x >> 5, lane = threadIdx.x & 31;
    __shared__ float sh[8][128];
    const float logpos = logf(fminf((float)(t + 1), 1024.0f));

    for (int h = w; h < NH + NKV; h += 8) {
        const float* row = g_qkv + (size_t)blk * QKV_N + h * 128;
        float v[4], ss = 0.f;
        #pragma unroll
        for (int j = 0; j < 4; j++) { v[j] = row[(lane << 2) + j]; ss += v[j] * v[j]; }
        #pragma unroll
        for (int o = 16; o > 0; o >>= 1) ss += __shfl_xor_sync(~0u, ss, o);
        const float r = rsqrtf(ss * (1.0f / 128.0f) + 1e-6f);
        #pragma unroll
        for (int j = 0; j < 4; j++) sh[w][(lane << 2) + j] = v[j] * r;
        __syncwarp();

        if (h < NH) {                                    // Q head: rope + scale
            const float sc = scaler[h] * logpos;
            float* qo = g_Q + ((size_t)((b * NH + h) * T_SEQ + t)) * DH;
            #pragma unroll
            for (int j = 0; j < 4; j++) {
                int d = (lane << 2) + j;
                float out;
                if (d < 64) out = sh[w][d];
                else {
                    int i = (d - 64) & 31;
                    float f = (float)t * inv_freq_f(i);
                    float c = cosf(f), s = sinf(f);
                    float x1 = sh[w][64 + i], x2 = sh[w][96 + i];
                    out = (d < 96) ? (x1 * c + x2 * s) : (-x1 * s + x2 * c);
                }
                qo[d] = sc * out;
            }
        } else {                                         // KV head: scatter tied K/V
            const int kvh = h - NH;
            float* ko = g_K + ((size_t)((b * NKV + kvh) * T_SEQ + t)) * DH;
            float* vo = g_V + ((size_t)((b * NKV + kvh) * T_SEQ + t)) * DH;
            #pragma unroll
            for (int j = 0; j < 4; j++) {
                int d = (lane << 2) + j;
                float val = sh[w][d];
                if (d < 64) { ko[d] = val; vo[d] = val; }
                else        { vo[d] = val; }
            }
        }
        __syncwarp();
    }

    // roped k_rope -> K dims 64..127 (same for all 4 kv heads)
    if (w == 0) {
        const float* rk = g_rkb + (size_t)blk * D2;
        float x1 = rk[lane], x2 = rk[lane + 32];
        float f = (float)t * inv_freq_f(lane);
        float c = cosf(f), s = sinf(f);
        float o1 = x1 * c + x2 * s, o2 = -x1 * s + x2 * c;
        #pragma unroll
        for (int kvh = 0; kvh < NKV; kvh++) {
            float* ko = g_K + ((size_t)((b * NKV + kvh) * T_SEQ + t)) * DH;
            ko[64 + lane] = o1;
            ko[96 + lane] = o2;
        }
    }
}

// ---------------- windowed flash attention, 32x32 tiles, fp32 ----------------
#define TQ 32
#define TK 32
__global__ void attn_kernel() {
    const int q0  = blockIdx.x * TQ;
    const int h   = blockIdx.y;
    const int b   = blockIdx.z;
    const int kvh = h >> 2;                  // repeat factor 4

    __shared__ float Qs [TQ][129];
    __shared__ float KVs[TK][129];
    __shared__ float Ssm[TQ][33];
    __shared__ float m_sh[TQ], l_sh[TQ], al_sh[TQ];

    const int tid = threadIdx.x;
    const float* Qg = g_Q + (size_t)((b * NH + h) * T_SEQ + q0) * DH;
    const float* Kg = g_K + (size_t)((b * NKV + kvh) * T_SEQ) * DH;
    const float* Vg = g_V + (size_t)((b * NKV + kvh) * T_SEQ) * DH;

    for (int i = tid; i < TQ * DH / 4; i += 256) {
        int r = i >> 5, c = (i & 31) << 2;
        float4 v = *(const float4*)(Qg + (size_t)r * DH + c);
        Qs[r][c] = v.x; Qs[r][c + 1] = v.y; Qs[r][c + 2] = v.z; Qs[r][c + 3] = v.w;
    }
    if (tid < TQ) { m_sh[tid] = -1e30f; l_sh[tid] = 0.f; }

    float acc[16];
    #pragma unroll
    for (int j = 0; j < 16; j++) acc[j] = 0.f;

    const int pw = tid >> 5, pl = tid & 31;          // PV mapping: q=pl, d=pw*16+j
    const int sq = tid >> 3, ss0 = (tid & 7) << 2;   // score mapping
    const int kstart = max(0, q0 - WSIZE);
    const float sscale = 0.08838834764831845f;       // 1/sqrt(128)
    __syncthreads();

    for (int k0 = kstart; k0 < q0 + TQ; k0 += TK) {
        for (int i = tid; i < TK * DH / 4; i += 256) {
            int r = i >> 5, c = (i & 31) << 2;
            float4 v = *(const float4*)(Kg + (size_t)(k0 + r) * DH + c);
            KVs[r][c] = v.x; KVs[r][c + 1] = v.y; KVs[r][c + 2] = v.z; KVs[r][c + 3] = v.w;
        }
        __syncthreads();

        // scores: each thread does 4 dot products (q=sq, s=ss0..ss0+3)
        float s4[4] = {0.f, 0.f, 0.f, 0.f};
        for (int k = 0; k < DH; k++) {
            float qv = Qs[sq][k];
            s4[0] += qv * KVs[ss0 + 0][k];
            s4[1] += qv * KVs[ss0 + 1][k];
            s4[2] += qv * KVs[ss0 + 2][k];
            s4[3] += qv * KVs[ss0 + 3][k];
        }
        const int gi = q0 + sq;
        #pragma unroll
        for (int c = 0; c < 4; c++) {
            int gj = k0 + ss0 + c;
            bool valid = (gj <= gi) && (gj >= gi - WSIZE);
            Ssm[sq][ss0 + c] = valid ? s4[c] * sscale : -1e30f;
        }
        __syncthreads();

        // online softmax: warp w owns rows 4w..4w+3
        {
            const int ww = tid >> 5, lane = tid & 31;
            #pragma unroll
            for (int r = 0; r < 4; r++) {
                int q = (ww << 2) + r;
                float val = Ssm[q][lane];
                float mx = val;
                #pragma unroll
                for (int o = 16; o > 0; o >>= 1) mx = fmaxf(mx, __shfl_xor_sync(~0u, mx, o));
                float mold = m_sh[q];
                float mnew = fmaxf(mold, mx);
                float p = (val > -1e29f) ? __expf(val - mnew) : 0.f;
                float su = p;
                #pragma unroll
                for (int o = 16; o > 0; o >>= 1) su += __shfl_xor_sync(~0u, su, o);
                if (lane == 0) {
                    float alpha = __expf(mold - mnew);
                    l_sh[q] = l_sh[q] * alpha + su;
                    m_sh[q] = mnew;
                    al_sh[q] = alpha;
                }
                Ssm[q][lane] = p;
            }
        }
        __syncthreads();

        // V tile (reuse KVs)
        for (int i = tid; i < TK * DH / 4; i += 256) {
            int r = i >> 5, c = (i & 31) << 2;
            float4 v = *(const float4*)(Vg + (size_t)(k0 + r) * DH + c);
            KVs[r][c] = v.x; KVs[r][c + 1] = v.y; KVs[r][c + 2] = v.z; KVs[r][c + 3] = v.w;
        }
        __syncthreads();

        // PV accumulate
        const float alpha = al_sh[pl];
        #pragma unroll
        for (int j = 0; j < 16; j++) acc[j] *= alpha;
        for (int s = 0; s < TK; s++) {
            float p = Ssm[pl][s];
            #pragma unroll
            for (int j = 0; j < 16; j++) acc[j] += p * KVs[s][(pw << 4) + j];
        }
        __syncthreads();
    }

    const float inv_l = 1.0f / l_sh[pl];
    float* Yo = g_Y + (size_t)((b * NH + h) * T_SEQ + q0 + pl) * DH + (pw << 4);
    #pragma unroll
    for (int j = 0; j < 16; j++) Yo[j] = acc[j] * inv_l;
}

// ---------------- out = y * silu(g) ----------------
__global__ void final_kernel(float* __restrict__ out) {
    const int o = blockIdx.x * 256 + threadIdx.x;   // total 8,388,608
    const float gv = g_gmat[o];
    const int d = o & 127;
    const int hh = (o >> 7) & 15;
    const int bt = o >> 11;                          // b*T + t
    const int t = bt & (T_SEQ - 1), b = bt >> 11;
    const float y = g_Y[(size_t)((b * NH + hh) * T_SEQ + t) * DH + d];
    out[o] = y * gv / (1.0f + expf(-gv));
}

// ---------------- launch ----------------
extern "C" void kernel_launch(void* const* d_in, const int* in_sizes, int n_in,
                              void* d_out, int out_size) {
    const float* x      = (const float*)d_in[0];
    const float* Wqkv   = (const float*)d_in[1];
    const float* Wrk    = (const float*)d_in[2];
    const float* brk    = (const float*)d_in[3];
    const float* scaler = (const float*)d_in[4];
    const float* Wg     = (const float*)d_in[5];
    float* out = (float*)d_out;

    float *p_qkv, *p_g;
    cudaGetSymbolAddress((void**)&p_qkv, g_qkv);
    cudaGetSymbolAddress((void**)&p_g,   g_gmat);

    gemm128<<<dim3(QKV_N / 128, BT / 128), 256>>>(x, Wqkv, p_qkv, QKV_N, D_MODEL);
    gemm128<<<dim3(D_MODEL / 128, BT / 128), 256>>>(x, Wg, p_g, D_MODEL, D_MODEL);
    rk_kernel<<<BT / 4, 256>>>(x, Wrk, brk);
    prep_kernel<<<BT, 256>>>(scaler);
    attn_kernel<<<dim3(T_SEQ / TQ, NH, B_SZ), 256>>>();
    final_kernel<<<(BT * D_MODEL) / 256, 256>>>(out);
}

// round 6
// speedup vs baseline: 1.4819x; 1.4819x over previous
#include <cuda_runtime.h>
#include <cuda_bf16.h>
#include <stdint.h>
#include <math.h>

#define D_MODEL 2048
#define NH      16
#define NKV     4
#define DH      128
#define D1      64
#define D2      64
#define T_SEQ   2048
#define B_SZ    2
#define BT      (B_SZ * T_SEQ)          // 4096
#define WSIZE   1024
#define QKV_N   ((NH + NKV) * DH)       // 2560

// ---------------- scratch (device globals; no runtime allocation) ----------------
__device__ float g_qkv [BT * QKV_N];                 // raw x@W_qkv
__device__ float g_rkb [BT * D2];                    // raw x@W_rk + b
__device__ float g_gmat[BT * D_MODEL];               // raw x@W_g
__device__ float g_Q   [B_SZ * NH  * T_SEQ * DH];
__device__ float g_K   [B_SZ * NKV * T_SEQ * DH];
__device__ float g_V   [B_SZ * NKV * T_SEQ * DH];
__device__ float g_Y   [B_SZ * NH  * T_SEQ * DH];

// split-bf16 operand copies
__device__ __nv_bfloat16 g_Ah [BT * D_MODEL];
__device__ __nv_bfloat16 g_Al [BT * D_MODEL];
__device__ __nv_bfloat16 g_Bqh[D_MODEL * QKV_N];
__device__ __nv_bfloat16 g_Bql[D_MODEL * QKV_N];
__device__ __nv_bfloat16 g_Bgh[D_MODEL * D_MODEL];
__device__ __nv_bfloat16 g_Bgl[D_MODEL * D_MODEL];

// ---------------- fp32 -> (hi, lo) bf16 split ----------------
__global__ void cvt_split(const float* __restrict__ src, __nv_bfloat16* __restrict__ hi,
                          __nv_bfloat16* __restrict__ lo, int n) {
    int i = blockIdx.x * 256 + threadIdx.x;
    if (i < n) {
        float f = src[i];
        __nv_bfloat16 h = __float2bfloat16(f);
        hi[i] = h;
        lo[i] = __float2bfloat16(f - __bfloat162float(h));
    }
}

// ---------------- tensor-core split-bf16 GEMM ----------------
// C[M,N] = A[M,K] * B[K,N], fp32 out, 3-product bf16 split.
// Block 128x128x32, 256 threads, warp tile 32x64.
#define BM 128
#define BN 128
#define BK 32
#define AST 40    // A smem row stride (bf16) -- conflict-free for ldmatrix
#define BST 136   // B smem row stride (bf16)

__device__ __forceinline__ void ldsm_x4(uint32_t* r, unsigned addr) {
    asm volatile("ldmatrix.sync.aligned.m8n8.x4.shared.b16 {%0,%1,%2,%3}, [%4];"
        : "=r"(r[0]), "=r"(r[1]), "=r"(r[2]), "=r"(r[3]) : "r"(addr));
}
__device__ __forceinline__ void ldsm_x4_t(uint32_t* r, unsigned addr) {
    asm volatile("ldmatrix.sync.aligned.m8n8.x4.trans.shared.b16 {%0,%1,%2,%3}, [%4];"
        : "=r"(r[0]), "=r"(r[1]), "=r"(r[2]), "=r"(r[3]) : "r"(addr));
}
__device__ __forceinline__ void mma_bf16(float* d, const uint32_t* a, const uint32_t* b) {
    asm volatile("mma.sync.aligned.m16n8k16.row.col.f32.bf16.bf16.f32 "
        "{%0,%1,%2,%3}, {%4,%5,%6,%7}, {%8,%9}, {%0,%1,%2,%3};"
        : "+f"(d[0]), "+f"(d[1]), "+f"(d[2]), "+f"(d[3])
        : "r"(a[0]), "r"(a[1]), "r"(a[2]), "r"(a[3]), "r"(b[0]), "r"(b[1]));
}

__global__ __launch_bounds__(256, 1)
void gemm_bf16x3(const __nv_bfloat16* __restrict__ Ah, const __nv_bfloat16* __restrict__ Al,
                 const __nv_bfloat16* __restrict__ Bh, const __nv_bfloat16* __restrict__ Bl,
                 float* __restrict__ C, int N, int K) {
    __shared__ __nv_bfloat16 As[2][BM * AST];
    __shared__ __nv_bfloat16 Bs[2][BK * BST];

    const int tid  = threadIdx.x;
    const int lane = tid & 31;
    const int wid  = tid >> 5;
    const int m0 = blockIdx.y * BM;
    const int n0 = blockIdx.x * BN;
    const int wm = (wid & 3) * 32;
    const int wn = (wid >> 2) * 64;

    const __nv_bfloat16* Aptr[2];
    Aptr[0] = Ah; Aptr[1] = Al;
    const __nv_bfloat16* Bptr[2];
    Bptr[0] = Bh; Bptr[1] = Bl;

    float acc[2][8][4];
    #pragma unroll
    for (int mf = 0; mf < 2; mf++) {
        #pragma unroll
        for (int nf = 0; nf < 8; nf++) {
            #pragma unroll
            for (int i = 0; i < 4; i++) { acc[mf][nf][i] = 0.f; }
        }
    }

    uint4 ra[2][2];
    uint4 rb[2][2];

    // prologue loads (k0 = 0)
    #pragma unroll
    for (int p = 0; p < 2; p++) {
        #pragma unroll
        for (int v = 0; v < 2; v++) {
            int vid = tid + v * 256;
            int ar = vid >> 2;
            int ac = (vid & 3) * 8;
            ra[p][v] = *(const uint4*)(Aptr[p] + (size_t)(m0 + ar) * K + ac);
            int br = vid >> 4;
            int bc = (vid & 15) * 8;
            rb[p][v] = *(const uint4*)(Bptr[p] + (size_t)br * N + n0 + bc);
        }
    }

    const unsigned a_base0 = (unsigned)__cvta_generic_to_shared(&As[0][0]);
    const unsigned a_base1 = (unsigned)__cvta_generic_to_shared(&As[1][0]);
    const unsigned b_base0 = (unsigned)__cvta_generic_to_shared(&Bs[0][0]);
    const unsigned b_base1 = (unsigned)__cvta_generic_to_shared(&Bs[1][0]);
    const int l15 = lane & 15;
    const int l16 = (lane >> 4) << 3;

    for (int k0 = 0; k0 < K; k0 += BK) {
        // commit staged regs to smem
        #pragma unroll
        for (int p = 0; p < 2; p++) {
            #pragma unroll
            for (int v = 0; v < 2; v++) {
                int vid = tid + v * 256;
                *(uint4*)&As[p][(vid >> 2) * AST + (vid & 3) * 8] = ra[p][v];
                *(uint4*)&Bs[p][(vid >> 4) * BST + (vid & 15) * 8] = rb[p][v];
            }
        }
        __syncthreads();

        // prefetch next K-chunk into registers (hidden under compute)
        if (k0 + BK < K) {
            int kn = k0 + BK;
            #pragma unroll
            for (int p = 0; p < 2; p++) {
                #pragma unroll
                for (int v = 0; v < 2; v++) {
                    int vid = tid + v * 256;
                    int ar = vid >> 2;
                    int ac = (vid & 3) * 8;
                    ra[p][v] = *(const uint4*)(Aptr[p] + (size_t)(m0 + ar) * K + kn + ac);
                    int br = vid >> 4;
                    int bc = (vid & 15) * 8;
                    rb[p][v] = *(const uint4*)(Bptr[p] + (size_t)(kn + br) * N + n0 + bc);
                }
            }
        }

        // compute on the tile
        #pragma unroll
        for (int kk = 0; kk < BK; kk += 16) {
            uint32_t afh[2][4];
            uint32_t afl[2][4];
            uint32_t bfh[8][2];
            uint32_t bfl[8][2];
            #pragma unroll
            for (int mf = 0; mf < 2; mf++) {
                unsigned off = (unsigned)((wm + mf * 16 + l15) * AST + kk + l16) * 2u;
                ldsm_x4(afh[mf], a_base0 + off);
                ldsm_x4(afl[mf], a_base1 + off);
            }
            #pragma unroll
            for (int nb = 0; nb < 4; nb++) {
                unsigned off = (unsigned)((kk + l15) * BST + wn + nb * 16 + l16) * 2u;
                uint32_t th[4];
                uint32_t tl[4];
                ldsm_x4_t(th, b_base0 + off);
                ldsm_x4_t(tl, b_base1 + off);
                bfh[2 * nb][0] = th[0]; bfh[2 * nb][1] = th[1];
                bfh[2 * nb + 1][0] = th[2]; bfh[2 * nb + 1][1] = th[3];
                bfl[2 * nb][0] = tl[0]; bfl[2 * nb][1] = tl[1];
                bfl[2 * nb + 1][0] = tl[2]; bfl[2 * nb + 1][1] = tl[3];
            }
            #pragma unroll
            for (int mf = 0; mf < 2; mf++) {
                #pragma unroll
                for (int nf = 0; nf < 8; nf++) {
                    mma_bf16(acc[mf][nf], afh[mf], bfh[nf]);
                    mma_bf16(acc[mf][nf], afl[mf], bfh[nf]);
                    mma_bf16(acc[mf][nf], afh[mf], bfl[nf]);
                }
            }
        }
        __syncthreads();
    }

    // epilogue
    const int grp = lane >> 2;
    const int t2  = (lane & 3) * 2;
    #pragma unroll
    for (int mf = 0; mf < 2; mf++) {
        #pragma unroll
        for (int nf = 0; nf < 8; nf++) {
            float* c0 = C + (size_t)(m0 + wm + mf * 16 + grp) * N + n0 + wn + nf * 8 + t2;
            *(float2*)c0 = make_float2(acc[mf][nf][0], acc[mf][nf][1]);
            float* c1 = c0 + (size_t)8 * N;
            *(float2*)c1 = make_float2(acc[mf][nf][2], acc[mf][nf][3]);
        }
    }
}

// ---------------- x @ W_rk + b_rk (N=64) ----------------
__global__ void rk_kernel(const float* __restrict__ X, const float* __restrict__ Wrk,
                          const float* __restrict__ brk) {
    const int tok0 = blockIdx.x << 2;
    __shared__ float xs[4][D_MODEL];
    for (int i = threadIdx.x; i < 4 * D_MODEL / 4; i += 256) {
        int tk = i >> 9;
        int cc = i & 511;
        ((float4*)xs[tk])[cc] = ((const float4*)(X + (size_t)(tok0 + tk) * D_MODEL))[cc];
    }
    __syncthreads();
    const int tk = threadIdx.x >> 6;
    const int n = threadIdx.x & 63;
    float acc = brk[n];
    for (int k = 0; k < D_MODEL; k++) { acc += xs[tk][k] * Wrk[k * 64 + n]; }
    g_rkb[(size_t)(tok0 + tk) * D2 + n] = acc;
}

// ---------------- rmsnorm + rope + scaling + KV scatter ----------------
__device__ __forceinline__ float inv_freq_f(int i) {
    return expf(-(float)i * 0.28782313662425575f);
}

__global__ void prep_kernel(const float* __restrict__ scaler) {
    const int blk = blockIdx.x;
    const int b = blk / T_SEQ;
    const int t = blk % T_SEQ;
    const int w = threadIdx.x >> 5;
    const int lane = threadIdx.x & 31;
    __shared__ float sh[8][128];
    const float logpos = logf(fminf((float)(t + 1), 1024.0f));

    for (int h = w; h < NH + NKV; h += 8) {
        const float* row = g_qkv + (size_t)blk * QKV_N + h * 128;
        float v[4];
        float ss = 0.f;
        #pragma unroll
        for (int j = 0; j < 4; j++) { v[j] = row[(lane << 2) + j]; ss += v[j] * v[j]; }
        #pragma unroll
        for (int o = 16; o > 0; o >>= 1) { ss += __shfl_xor_sync(~0u, ss, o); }
        const float r = rsqrtf(ss * (1.0f / 128.0f) + 1e-6f);
        #pragma unroll
        for (int j = 0; j < 4; j++) { sh[w][(lane << 2) + j] = v[j] * r; }
        __syncwarp();

        if (h < NH) {
            const float sc = scaler[h] * logpos;
            float* qo = g_Q + ((size_t)((b * NH + h) * T_SEQ + t)) * DH;
            #pragma unroll
            for (int j = 0; j < 4; j++) {
                int d = (lane << 2) + j;
                float outv;
                if (d < 64) {
                    outv = sh[w][d];
                } else {
                    int i = (d - 64) & 31;
                    float f = (float)t * inv_freq_f(i);
                    float c = cosf(f);
                    float s = sinf(f);
                    float x1 = sh[w][64 + i];
                    float x2 = sh[w][96 + i];
                    outv = (d < 96) ? (x1 * c + x2 * s) : (-x1 * s + x2 * c);
                }
                qo[d] = sc * outv;
            }
        } else {
            const int kvh = h - NH;
            float* ko = g_K + ((size_t)((b * NKV + kvh) * T_SEQ + t)) * DH;
            float* vo = g_V + ((size_t)((b * NKV + kvh) * T_SEQ + t)) * DH;
            #pragma unroll
            for (int j = 0; j < 4; j++) {
                int d = (lane << 2) + j;
                float val = sh[w][d];
                if (d < 64) { ko[d] = val; vo[d] = val; }
                else        { vo[d] = val; }
            }
        }
        __syncwarp();
    }

    if (w == 0) {
        const float* rk = g_rkb + (size_t)blk * D2;
        float x1 = rk[lane];
        float x2 = rk[lane + 32];
        float f = (float)t * inv_freq_f(lane);
        float c = cosf(f);
        float s = sinf(f);
        float o1 = x1 * c + x2 * s;
        float o2 = -x1 * s + x2 * c;
        #pragma unroll
        for (int kvh = 0; kvh < NKV; kvh++) {
            float* ko = g_K + ((size_t)((b * NKV + kvh) * T_SEQ + t)) * DH;
            ko[64 + lane] = o1;
            ko[96 + lane] = o2;
        }
    }
}

// ---------------- windowed flash attention, 32x32 tiles, fp32 ----------------
#define TQ 32
#define TK 32
__global__ void attn_kernel() {
    const int q0  = blockIdx.x * TQ;
    const int h   = blockIdx.y;
    const int b   = blockIdx.z;
    const int kvh = h >> 2;

    __shared__ float Qs [TQ][129];
    __shared__ float KVs[TK][129];
    __shared__ float Ssm[TQ][33];
    __shared__ float m_sh[TQ];
    __shared__ float l_sh[TQ];
    __shared__ float al_sh[TQ];

    const int tid = threadIdx.x;
    const float* Qg = g_Q + (size_t)((b * NH + h) * T_SEQ + q0) * DH;
    const float* Kg = g_K + (size_t)((b * NKV + kvh) * T_SEQ) * DH;
    const float* Vg = g_V + (size_t)((b * NKV + kvh) * T_SEQ) * DH;

    for (int i = tid; i < TQ * DH / 4; i += 256) {
        int r = i >> 5;
        int c = (i & 31) << 2;
        float4 v = *(const float4*)(Qg + (size_t)r * DH + c);
        Qs[r][c] = v.x; Qs[r][c + 1] = v.y; Qs[r][c + 2] = v.z; Qs[r][c + 3] = v.w;
    }
    if (tid < TQ) { m_sh[tid] = -1e30f; l_sh[tid] = 0.f; }

    float acc[16];
    #pragma unroll
    for (int j = 0; j < 16; j++) { acc[j] = 0.f; }

    const int pw = tid >> 5;
    const int pl = tid & 31;
    const int sq = tid >> 3;
    const int ss0 = (tid & 7) << 2;
    const int kstart = max(0, q0 - WSIZE);
    const float sscale = 0.08838834764831845f;
    __syncthreads();

    for (int k0 = kstart; k0 < q0 + TQ; k0 += TK) {
        for (int i = tid; i < TK * DH / 4; i += 256) {
            int r = i >> 5;
            int c = (i & 31) << 2;
            float4 v = *(const float4*)(Kg + (size_t)(k0 + r) * DH + c);
            KVs[r][c] = v.x; KVs[r][c + 1] = v.y; KVs[r][c + 2] = v.z; KVs[r][c + 3] = v.w;
        }
        __syncthreads();

        float s4[4] = {0.f, 0.f, 0.f, 0.f};
        for (int k = 0; k < DH; k++) {
            float qv = Qs[sq][k];
            s4[0] += qv * KVs[ss0 + 0][k];
            s4[1] += qv * KVs[ss0 + 1][k];
            s4[2] += qv * KVs[ss0 + 2][k];
            s4[3] += qv * KVs[ss0 + 3][k];
        }
        const int gi = q0 + sq;
        #pragma unroll
        for (int c = 0; c < 4; c++) {
            int gj = k0 + ss0 + c;
            bool valid = (gj <= gi) && (gj >= gi - WSIZE);
            Ssm[sq][ss0 + c] = valid ? s4[c] * sscale : -1e30f;
        }
        __syncthreads();

        {
            const int ww = tid >> 5;
            const int lane = tid & 31;
            #pragma unroll
            for (int r = 0; r < 4; r++) {
                int q = (ww << 2) + r;
                float val = Ssm[q][lane];
                float mx = val;
                #pragma unroll
                for (int o = 16; o > 0; o >>= 1) { mx = fmaxf(mx, __shfl_xor_sync(~0u, mx, o)); }
                float mold = m_sh[q];
                float mnew = fmaxf(mold, mx);
                float p = (val > -1e29f) ? __expf(val - mnew) : 0.f;
                float su = p;
                #pragma unroll
                for (int o = 16; o > 0; o >>= 1) { su += __shfl_xor_sync(~0u, su, o); }
                if (lane == 0) {
                    float alpha = __expf(mold - mnew);
                    l_sh[q] = l_sh[q] * alpha + su;
                    m_sh[q] = mnew;
                    al_sh[q] = alpha;
                }
                Ssm[q][lane] = p;
            }
        }
        __syncthreads();

        for (int i = tid; i < TK * DH / 4; i += 256) {
            int r = i >> 5;
            int c = (i & 31) << 2;
            float4 v = *(const float4*)(Vg + (size_t)(k0 + r) * DH + c);
            KVs[r][c] = v.x; KVs[r][c + 1] = v.y; KVs[r][c + 2] = v.z; KVs[r][c + 3] = v.w;
        }
        __syncthreads();

        const float alpha = al_sh[pl];
        #pragma unroll
        for (int j = 0; j < 16; j++) { acc[j] *= alpha; }
        for (int s = 0; s < TK; s++) {
            float p = Ssm[pl][s];
            #pragma unroll
            for (int j = 0; j < 16; j++) { acc[j] += p * KVs[s][(pw << 4) + j]; }
        }
        __syncthreads();
    }

    const float inv_l = 1.0f / l_sh[pl];
    float* Yo = g_Y + (size_t)((b * NH + h) * T_SEQ + q0 + pl) * DH + (pw << 4);
    #pragma unroll
    for (int j = 0; j < 16; j++) { Yo[j] = acc[j] * inv_l; }
}

// ---------------- out = y * silu(g) ----------------
__global__ void final_kernel(float* __restrict__ out) {
    const int o = blockIdx.x * 256 + threadIdx.x;
    const float gv = g_gmat[o];
    const int d = o & 127;
    const int hh = (o >> 7) & 15;
    const int bt = o >> 11;
    const int t = bt & (T_SEQ - 1);
    const int b = bt >> 11;
    const float y = g_Y[(size_t)((b * NH + hh) * T_SEQ + t) * DH + d];
    out[o] = y * gv / (1.0f + expf(-gv));
}

// ---------------- launch ----------------
extern "C" void kernel_launch(void* const* d_in, const int* in_sizes, int n_in,
                              void* d_out, int out_size) {
    const float* x      = (const float*)d_in[0];
    const float* Wqkv   = (const float*)d_in[1];
    const float* Wrk    = (const float*)d_in[2];
    const float* brk    = (const float*)d_in[3];
    const float* scaler = (const float*)d_in[4];
    const float* Wg     = (const float*)d_in[5];
    float* out = (float*)d_out;

    float* p_qkv;
    float* p_g;
    __nv_bfloat16* p_Ah;
    __nv_bfloat16* p_Al;
    __nv_bfloat16* p_Bqh;
    __nv_bfloat16* p_Bql;
    __nv_bfloat16* p_Bgh;
    __nv_bfloat16* p_Bgl;
    cudaGetSymbolAddress((void**)&p_qkv, g_qkv);
    cudaGetSymbolAddress((void**)&p_g,   g_gmat);
    cudaGetSymbolAddress((void**)&p_Ah,  g_Ah);
    cudaGetSymbolAddress((void**)&p_Al,  g_Al);
    cudaGetSymbolAddress((void**)&p_Bqh, g_Bqh);
    cudaGetSymbolAddress((void**)&p_Bql, g_Bql);
    cudaGetSymbolAddress((void**)&p_Bgh, g_Bgh);
    cudaGetSymbolAddress((void**)&p_Bgl, g_Bgl);

    // split-precision conversion pre-pass
    cvt_split<<<(BT * D_MODEL + 255) / 256, 256>>>(x, p_Ah, p_Al, BT * D_MODEL);
    cvt_split<<<(D_MODEL * QKV_N + 255) / 256, 256>>>(Wqkv, p_Bqh, p_Bql, D_MODEL * QKV_N);
    cvt_split<<<(D_MODEL * D_MODEL + 255) / 256, 256>>>(Wg, p_Bgh, p_Bgl, D_MODEL * D_MODEL);

    // tensor-core GEMMs
    gemm_bf16x3<<<dim3(QKV_N / BN, BT / BM), 256>>>(p_Ah, p_Al, p_Bqh, p_Bql, p_qkv, QKV_N, D_MODEL);
    gemm_bf16x3<<<dim3(D_MODEL / BN, BT / BM), 256>>>(p_Ah, p_Al, p_Bgh, p_Bgl, p_g, D_MODEL, D_MODEL);

    rk_kernel<<<BT / 4, 256>>>(x, Wrk, brk);
    prep_kernel<<<BT, 256>>>(scaler);
    attn_kernel<<<dim3(T_SEQ / TQ, NH, B_SZ), 256>>>();
    final_kernel<<<(BT * D_MODEL) / 256, 256>>>(out);
}

// round 7
// speedup vs baseline: 3.3319x; 2.2484x over previous
#include <cuda_runtime.h>
#include <cuda_bf16.h>
#include <stdint.h>
#include <math.h>

#define D_MODEL 2048
#define NH      16
#define NKV     4
#define DH      128
#define D1      64
#define D2      64
#define T_SEQ   2048
#define B_SZ    2
#define BT      (B_SZ * T_SEQ)          // 4096
#define WSIZE   1024
#define QKV_N   ((NH + NKV) * DH)       // 2560

// ---------------- scratch (device globals; no runtime allocation) ----------------
__device__ float g_qkv [BT * QKV_N];                 // raw x@W_qkv
__device__ float g_rkb [BT * D2];                    // raw x@W_rk + b
__device__ float g_gmat[BT * D_MODEL];               // raw x@W_g
__device__ float g_Y   [B_SZ * NH  * T_SEQ * DH];

// split-bf16 Q/K/V
__device__ __nv_bfloat16 g_Qh[B_SZ * NH  * T_SEQ * DH];
__device__ __nv_bfloat16 g_Ql[B_SZ * NH  * T_SEQ * DH];
__device__ __nv_bfloat16 g_Kh[B_SZ * NKV * T_SEQ * DH];
__device__ __nv_bfloat16 g_Kl[B_SZ * NKV * T_SEQ * DH];
__device__ __nv_bfloat16 g_Vh[B_SZ * NKV * T_SEQ * DH];
__device__ __nv_bfloat16 g_Vl[B_SZ * NKV * T_SEQ * DH];

// split-bf16 GEMM operand copies
__device__ __nv_bfloat16 g_Ah [BT * D_MODEL];
__device__ __nv_bfloat16 g_Al [BT * D_MODEL];
__device__ __nv_bfloat16 g_Bqh[D_MODEL * QKV_N];
__device__ __nv_bfloat16 g_Bql[D_MODEL * QKV_N];
__device__ __nv_bfloat16 g_Bgh[D_MODEL * D_MODEL];
__device__ __nv_bfloat16 g_Bgl[D_MODEL * D_MODEL];

// ---------------- fp32 -> (hi, lo) bf16 split ----------------
__global__ void cvt_split(const float* __restrict__ src, __nv_bfloat16* __restrict__ hi,
                          __nv_bfloat16* __restrict__ lo, int n) {
    int i = blockIdx.x * 256 + threadIdx.x;
    if (i < n) {
        float f = src[i];
        __nv_bfloat16 h = __float2bfloat16(f);
        hi[i] = h;
        lo[i] = __float2bfloat16(f - __bfloat162float(h));
    }
}

// ---------------- mma / ldmatrix helpers ----------------
__device__ __forceinline__ void ldsm_x4(uint32_t* r, unsigned addr) {
    asm volatile("ldmatrix.sync.aligned.m8n8.x4.shared.b16 {%0,%1,%2,%3}, [%4];"
        : "=r"(r[0]), "=r"(r[1]), "=r"(r[2]), "=r"(r[3]) : "r"(addr));
}
__device__ __forceinline__ void ldsm_x4_t(uint32_t* r, unsigned addr) {
    asm volatile("ldmatrix.sync.aligned.m8n8.x4.trans.shared.b16 {%0,%1,%2,%3}, [%4];"
        : "=r"(r[0]), "=r"(r[1]), "=r"(r[2]), "=r"(r[3]) : "r"(addr));
}
__device__ __forceinline__ void mma_bf16(float* d, const uint32_t* a, const uint32_t* b) {
    asm volatile("mma.sync.aligned.m16n8k16.row.col.f32.bf16.bf16.f32 "
        "{%0,%1,%2,%3}, {%4,%5,%6,%7}, {%8,%9}, {%0,%1,%2,%3};"
        : "+f"(d[0]), "+f"(d[1]), "+f"(d[2]), "+f"(d[3])
        : "r"(a[0]), "r"(a[1]), "r"(a[2]), "r"(a[3]), "r"(b[0]), "r"(b[1]));
}
__device__ __forceinline__ uint32_t pack_bf16x2(float x, float y) {
    __nv_bfloat162 t = __floats2bfloat162_rn(x, y);
    return *(uint32_t*)&t;
}

// ---------------- tensor-core split-bf16 GEMM ----------------
#define BM 128
#define BN 128
#define BK 32
#define AST 40
#define BST 136

__global__ __launch_bounds__(256, 1)
void gemm_bf16x3(const __nv_bfloat16* __restrict__ Ah, const __nv_bfloat16* __restrict__ Al,
                 const __nv_bfloat16* __restrict__ Bh, const __nv_bfloat16* __restrict__ Bl,
                 float* __restrict__ C, int N, int K) {
    __shared__ __nv_bfloat16 As[2][BM * AST];
    __shared__ __nv_bfloat16 Bs[2][BK * BST];

    const int tid  = threadIdx.x;
    const int lane = tid & 31;
    const int wid  = tid >> 5;
    const int m0 = blockIdx.y * BM;
    const int n0 = blockIdx.x * BN;
    const int wm = (wid & 3) * 32;
    const int wn = (wid >> 2) * 64;

    const __nv_bfloat16* Aptr[2];
    Aptr[0] = Ah; Aptr[1] = Al;
    const __nv_bfloat16* Bptr[2];
    Bptr[0] = Bh; Bptr[1] = Bl;

    float acc[2][8][4];
    #pragma unroll
    for (int mf = 0; mf < 2; mf++) {
        #pragma unroll
        for (int nf = 0; nf < 8; nf++) {
            #pragma unroll
            for (int i = 0; i < 4; i++) { acc[mf][nf][i] = 0.f; }
        }
    }

    uint4 ra[2][2];
    uint4 rb[2][2];

    #pragma unroll
    for (int p = 0; p < 2; p++) {
        #pragma unroll
        for (int v = 0; v < 2; v++) {
            int vid = tid + v * 256;
            int ar = vid >> 2;
            int ac = (vid & 3) * 8;
            ra[p][v] = *(const uint4*)(Aptr[p] + (size_t)(m0 + ar) * K + ac);
            int br = vid >> 4;
            int bc = (vid & 15) * 8;
            rb[p][v] = *(const uint4*)(Bptr[p] + (size_t)br * N + n0 + bc);
        }
    }

    const unsigned a_base0 = (unsigned)__cvta_generic_to_shared(&As[0][0]);
    const unsigned a_base1 = (unsigned)__cvta_generic_to_shared(&As[1][0]);
    const unsigned b_base0 = (unsigned)__cvta_generic_to_shared(&Bs[0][0]);
    const unsigned b_base1 = (unsigned)__cvta_generic_to_shared(&Bs[1][0]);
    const int l15 = lane & 15;
    const int l16 = (lane >> 4) << 3;

    for (int k0 = 0; k0 < K; k0 += BK) {
        #pragma unroll
        for (int p = 0; p < 2; p++) {
            #pragma unroll
            for (int v = 0; v < 2; v++) {
                int vid = tid + v * 256;
                *(uint4*)&As[p][(vid >> 2) * AST + (vid & 3) * 8] = ra[p][v];
                *(uint4*)&Bs[p][(vid >> 4) * BST + (vid & 15) * 8] = rb[p][v];
            }
        }
        __syncthreads();

        if (k0 + BK < K) {
            int kn = k0 + BK;
            #pragma unroll
            for (int p = 0; p < 2; p++) {
                #pragma unroll
                for (int v = 0; v < 2; v++) {
                    int vid = tid + v * 256;
                    int ar = vid >> 2;
                    int ac = (vid & 3) * 8;
                    ra[p][v] = *(const uint4*)(Aptr[p] + (size_t)(m0 + ar) * K + kn + ac);
                    int br = vid >> 4;
                    int bc = (vid & 15) * 8;
                    rb[p][v] = *(const uint4*)(Bptr[p] + (size_t)(kn + br) * N + n0 + bc);
                }
            }
        }

        #pragma unroll
        for (int kk = 0; kk < BK; kk += 16) {
            uint32_t afh[2][4];
            uint32_t afl[2][4];
            uint32_t bfh[8][2];
            uint32_t bfl[8][2];
            #pragma unroll
            for (int mf = 0; mf < 2; mf++) {
                unsigned off = (unsigned)((wm + mf * 16 + l15) * AST + kk + l16) * 2u;
                ldsm_x4(afh[mf], a_base0 + off);
                ldsm_x4(afl[mf], a_base1 + off);
            }
            #pragma unroll
            for (int nb = 0; nb < 4; nb++) {
                unsigned off = (unsigned)((kk + l15) * BST + wn + nb * 16 + l16) * 2u;
                uint32_t th[4];
                uint32_t tl[4];
                ldsm_x4_t(th, b_base0 + off);
                ldsm_x4_t(tl, b_base1 + off);
                bfh[2 * nb][0] = th[0]; bfh[2 * nb][1] = th[1];
                bfh[2 * nb + 1][0] = th[2]; bfh[2 * nb + 1][1] = th[3];
                bfl[2 * nb][0] = tl[0]; bfl[2 * nb][1] = tl[1];
                bfl[2 * nb + 1][0] = tl[2]; bfl[2 * nb + 1][1] = tl[3];
            }
            #pragma unroll
            for (int mf = 0; mf < 2; mf++) {
                #pragma unroll
                for (int nf = 0; nf < 8; nf++) {
                    mma_bf16(acc[mf][nf], afh[mf], bfh[nf]);
                    mma_bf16(acc[mf][nf], afl[mf], bfh[nf]);
                    mma_bf16(acc[mf][nf], afh[mf], bfl[nf]);
                }
            }
        }
        __syncthreads();
    }

    const int grp = lane >> 2;
    const int t2  = (lane & 3) * 2;
    #pragma unroll
    for (int mf = 0; mf < 2; mf++) {
        #pragma unroll
        for (int nf = 0; nf < 8; nf++) {
            float* c0 = C + (size_t)(m0 + wm + mf * 16 + grp) * N + n0 + wn + nf * 8 + t2;
            *(float2*)c0 = make_float2(acc[mf][nf][0], acc[mf][nf][1]);
            float* c1 = c0 + (size_t)8 * N;
            *(float2*)c1 = make_float2(acc[mf][nf][2], acc[mf][nf][3]);
        }
    }
}

// ---------------- x @ W_rk + b_rk (N=64) ----------------
__global__ void rk_kernel(const float* __restrict__ X, const float* __restrict__ Wrk,
                          const float* __restrict__ brk) {
    const int tok0 = blockIdx.x << 2;
    __shared__ float xs[4][D_MODEL];
    for (int i = threadIdx.x; i < 4 * D_MODEL / 4; i += 256) {
        int tk = i >> 9;
        int cc = i & 511;
        ((float4*)xs[tk])[cc] = ((const float4*)(X + (size_t)(tok0 + tk) * D_MODEL))[cc];
    }
    __syncthreads();
    const int tk = threadIdx.x >> 6;
    const int n = threadIdx.x & 63;
    float acc = brk[n];
    for (int k = 0; k < D_MODEL; k++) { acc += xs[tk][k] * Wrk[k * 64 + n]; }
    g_rkb[(size_t)(tok0 + tk) * D2 + n] = acc;
}

// ---------------- rmsnorm + rope + scaling + KV scatter (bf16 split out) ----------------
__device__ __forceinline__ float inv_freq_f(int i) {
    return expf(-(float)i * 0.28782313662425575f);
}
__device__ __forceinline__ void store_split(__nv_bfloat16* hi, __nv_bfloat16* lo,
                                            size_t idx, float v) {
    __nv_bfloat16 h = __float2bfloat16(v);
    hi[idx] = h;
    lo[idx] = __float2bfloat16(v - __bfloat162float(h));
}

__global__ void prep_kernel(const float* __restrict__ scaler) {
    const int blk = blockIdx.x;
    const int b = blk / T_SEQ;
    const int t = blk % T_SEQ;
    const int w = threadIdx.x >> 5;
    const int lane = threadIdx.x & 31;
    __shared__ float sh[8][128];
    const float logpos = logf(fminf((float)(t + 1), 1024.0f));

    for (int h = w; h < NH + NKV; h += 8) {
        const float* row = g_qkv + (size_t)blk * QKV_N + h * 128;
        float v[4];
        float ss = 0.f;
        #pragma unroll
        for (int j = 0; j < 4; j++) { v[j] = row[(lane << 2) + j]; ss += v[j] * v[j]; }
        #pragma unroll
        for (int o = 16; o > 0; o >>= 1) { ss += __shfl_xor_sync(~0u, ss, o); }
        const float r = rsqrtf(ss * (1.0f / 128.0f) + 1e-6f);
        #pragma unroll
        for (int j = 0; j < 4; j++) { sh[w][(lane << 2) + j] = v[j] * r; }
        __syncwarp();

        if (h < NH) {
            const float sc = scaler[h] * logpos;
            size_t qbase = ((size_t)((b * NH + h) * T_SEQ + t)) * DH;
            #pragma unroll
            for (int j = 0; j < 4; j++) {
                int d = (lane << 2) + j;
                float outv;
                if (d < 64) {
                    outv = sh[w][d];
                } else {
                    int i = (d - 64) & 31;
                    float f = (float)t * inv_freq_f(i);
                    float c = cosf(f);
                    float s = sinf(f);
                    float x1 = sh[w][64 + i];
                    float x2 = sh[w][96 + i];
                    outv = (d < 96) ? (x1 * c + x2 * s) : (-x1 * s + x2 * c);
                }
                store_split(g_Qh, g_Ql, qbase + d, sc * outv);
            }
        } else {
            const int kvh = h - NH;
            size_t kvbase = ((size_t)((b * NKV + kvh) * T_SEQ + t)) * DH;
            #pragma unroll
            for (int j = 0; j < 4; j++) {
                int d = (lane << 2) + j;
                float val = sh[w][d];
                if (d < 64) {
                    store_split(g_Kh, g_Kl, kvbase + d, val);
                    store_split(g_Vh, g_Vl, kvbase + d, val);
                } else {
                    store_split(g_Vh, g_Vl, kvbase + d, val);
                }
            }
        }
        __syncwarp();
    }

    if (w == 0) {
        const float* rk = g_rkb + (size_t)blk * D2;
        float x1 = rk[lane];
        float x2 = rk[lane + 32];
        float f = (float)t * inv_freq_f(lane);
        float c = cosf(f);
        float s = sinf(f);
        float o1 = x1 * c + x2 * s;
        float o2 = -x1 * s + x2 * c;
        #pragma unroll
        for (int kvh = 0; kvh < NKV; kvh++) {
            size_t kvbase = ((size_t)((b * NKV + kvh) * T_SEQ + t)) * DH;
            store_split(g_Kh, g_Kl, kvbase + 64 + lane, o1);
            store_split(g_Kh, g_Kl, kvbase + 96 + lane, o2);
        }
    }
}

// ---------------- tensor-core windowed flash attention ----------------
// 128 q-rows per block, 8 warps x m16, TK=32 key tiles, split-bf16 3-product.
#define ATQ 128
#define ATK 32
#define KST 136

__global__ __launch_bounds__(256, 1) void attn_kernel() {
    const int q0  = blockIdx.x * ATQ;
    const int h   = blockIdx.y;
    const int b   = blockIdx.z;
    const int kvh = h >> 2;

    __shared__ __nv_bfloat16 skh[ATK * KST];
    __shared__ __nv_bfloat16 skl[ATK * KST];
    __shared__ __nv_bfloat16 svh[ATK * KST];
    __shared__ __nv_bfloat16 svl[ATK * KST];

    const int tid  = threadIdx.x;
    const int lane = tid & 31;
    const int wid  = tid >> 5;
    const int wm   = wid << 4;            // warp rows [wm, wm+16)
    const int g    = lane >> 2;
    const int t2   = (lane & 3) << 1;
    const int l15  = lane & 15;
    const int l16o = (lane >> 4) << 3;

    // ---- Q fragments in registers (hi, lo), 8 k-chunks ----
    const __nv_bfloat16* Qhp = g_Qh + ((size_t)((b * NH + h) * T_SEQ + q0 + wm)) * DH;
    const __nv_bfloat16* Qlp = g_Ql + ((size_t)((b * NH + h) * T_SEQ + q0 + wm)) * DH;
    uint32_t qh[8][4];
    uint32_t ql[8][4];
    #pragma unroll
    for (int kk = 0; kk < 8; kk++) {
        int c0 = kk * 16 + t2;
        qh[kk][0] = *(const uint32_t*)(Qhp + (size_t)g * DH + c0);
        qh[kk][1] = *(const uint32_t*)(Qhp + (size_t)(g + 8) * DH + c0);
        qh[kk][2] = *(const uint32_t*)(Qhp + (size_t)g * DH + c0 + 8);
        qh[kk][3] = *(const uint32_t*)(Qhp + (size_t)(g + 8) * DH + c0 + 8);
        ql[kk][0] = *(const uint32_t*)(Qlp + (size_t)g * DH + c0);
        ql[kk][1] = *(const uint32_t*)(Qlp + (size_t)(g + 8) * DH + c0);
        ql[kk][2] = *(const uint32_t*)(Qlp + (size_t)g * DH + c0 + 8);
        ql[kk][3] = *(const uint32_t*)(Qlp + (size_t)(g + 8) * DH + c0 + 8);
    }

    const __nv_bfloat16* Khp = g_Kh + ((size_t)((b * NKV + kvh) * T_SEQ)) * DH;
    const __nv_bfloat16* Klp = g_Kl + ((size_t)((b * NKV + kvh) * T_SEQ)) * DH;
    const __nv_bfloat16* Vhp = g_Vh + ((size_t)((b * NKV + kvh) * T_SEQ)) * DH;
    const __nv_bfloat16* Vlp = g_Vl + ((size_t)((b * NKV + kvh) * T_SEQ)) * DH;

    const unsigned skh_b = (unsigned)__cvta_generic_to_shared(skh);
    const unsigned skl_b = (unsigned)__cvta_generic_to_shared(skl);
    const unsigned svh_b = (unsigned)__cvta_generic_to_shared(svh);
    const unsigned svl_b = (unsigned)__cvta_generic_to_shared(svl);

    float o[16][4];
    #pragma unroll
    for (int nf = 0; nf < 16; nf++) {
        #pragma unroll
        for (int i = 0; i < 4; i++) { o[nf][i] = 0.f; }
    }
    float m0 = -1e30f;
    float m1 = -1e30f;
    float l0 = 0.f;
    float l1 = 0.f;

    const int gi0 = q0 + wm + g;
    const int gi1 = gi0 + 8;
    const int kstart = (q0 >= WSIZE) ? (q0 - WSIZE) : 0;
    const float sscale = 0.08838834764831845f;   // 1/sqrt(128)

    for (int k0 = kstart; k0 < q0 + ATQ; k0 += ATK) {
        // ---- cooperative K/V tile load (32 x 128 bf16 x4 arrays) ----
        #pragma unroll
        for (int v = 0; v < 2; v++) {
            int idx = tid + v * 256;              // 0..511
            int r = idx >> 4;
            int c = (idx & 15) << 3;
            size_t goff = (size_t)(k0 + r) * DH + c;
            int soff = r * KST + c;
            *(uint4*)&skh[soff] = *(const uint4*)(Khp + goff);
            *(uint4*)&skl[soff] = *(const uint4*)(Klp + goff);
            *(uint4*)&svh[soff] = *(const uint4*)(Vhp + goff);
            *(uint4*)&svl[soff] = *(const uint4*)(Vlp + goff);
        }
        __syncthreads();

        // ---- S = Q K^T (split 3-product), S: m16 x n32 per warp ----
        float s[4][4];
        #pragma unroll
        for (int nb = 0; nb < 4; nb++) {
            #pragma unroll
            for (int i = 0; i < 4; i++) { s[nb][i] = 0.f; }
        }
        #pragma unroll
        for (int kk = 0; kk < 8; kk++) {
            uint32_t kh0[4], kh1[4], kl0[4], kl1[4];
            unsigned off0 = (unsigned)((l15) * KST + kk * 16 + l16o) * 2u;
            unsigned off1 = (unsigned)((16 + l15) * KST + kk * 16 + l16o) * 2u;
            ldsm_x4(kh0, skh_b + off0);
            ldsm_x4(kh1, skh_b + off1);
            ldsm_x4(kl0, skl_b + off0);
            ldsm_x4(kl1, skl_b + off1);
            uint32_t bh[4][2];
            uint32_t bl[4][2];
            bh[0][0] = kh0[0]; bh[0][1] = kh0[2];
            bh[1][0] = kh0[1]; bh[1][1] = kh0[3];
            bh[2][0] = kh1[0]; bh[2][1] = kh1[2];
            bh[3][0] = kh1[1]; bh[3][1] = kh1[3];
            bl[0][0] = kl0[0]; bl[0][1] = kl0[2];
            bl[1][0] = kl0[1]; bl[1][1] = kl0[3];
            bl[2][0] = kl1[0]; bl[2][1] = kl1[2];
            bl[3][0] = kl1[1]; bl[3][1] = kl1[3];
            #pragma unroll
            for (int nb = 0; nb < 4; nb++) {
                mma_bf16(s[nb], qh[kk], bh[nb]);
                mma_bf16(s[nb], ql[kk], bh[nb]);
                mma_bf16(s[nb], qh[kk], bl[nb]);
            }
        }

        // ---- mask + online softmax (rows g and g+8, warp-local) ----
        float mx0 = -1e30f;
        float mx1 = -1e30f;
        #pragma unroll
        for (int nb = 0; nb < 4; nb++) {
            #pragma unroll
            for (int ii = 0; ii < 2; ii++) {
                int j = k0 + nb * 8 + t2 + ii;
                float v0 = (j <= gi0 && j >= gi0 - WSIZE) ? s[nb][ii] * sscale : -1e30f;
                float v1 = (j <= gi1 && j >= gi1 - WSIZE) ? s[nb][2 + ii] * sscale : -1e30f;
                s[nb][ii] = v0;
                s[nb][2 + ii] = v1;
                mx0 = fmaxf(mx0, v0);
                mx1 = fmaxf(mx1, v1);
            }
        }
        mx0 = fmaxf(mx0, __shfl_xor_sync(~0u, mx0, 1));
        mx0 = fmaxf(mx0, __shfl_xor_sync(~0u, mx0, 2));
        mx1 = fmaxf(mx1, __shfl_xor_sync(~0u, mx1, 1));
        mx1 = fmaxf(mx1, __shfl_xor_sync(~0u, mx1, 2));
        float mn0 = fmaxf(m0, mx0);
        float mn1 = fmaxf(m1, mx1);
        float a0 = __expf(m0 - mn0);
        float a1 = __expf(m1 - mn1);
        m0 = mn0;
        m1 = mn1;

        float su0 = 0.f;
        float su1 = 0.f;
        uint32_t ph[2][4];
        uint32_t pl[2][4];
        #pragma unroll
        for (int nb = 0; nb < 4; nb++) {
            float p0 = __expf(s[nb][0] - mn0);
            float p1 = __expf(s[nb][1] - mn0);
            float p2 = __expf(s[nb][2] - mn1);
            float p3 = __expf(s[nb][3] - mn1);
            su0 += p0 + p1;
            su1 += p2 + p3;
            int c = nb >> 1;
            int half = (nb & 1) << 1;
            uint32_t h01 = pack_bf16x2(p0, p1);
            uint32_t h23 = pack_bf16x2(p2, p3);
            ph[c][half]     = h01;
            ph[c][half + 1] = h23;
            __nv_bfloat162* hp01 = (__nv_bfloat162*)&h01;
            __nv_bfloat162* hp23 = (__nv_bfloat162*)&h23;
            pl[c][half]     = pack_bf16x2(p0 - __bfloat162float(hp01->x),
                                          p1 - __bfloat162float(hp01->y));
            pl[c][half + 1] = pack_bf16x2(p2 - __bfloat162float(hp23->x),
                                          p3 - __bfloat162float(hp23->y));
        }
        su0 += __shfl_xor_sync(~0u, su0, 1);
        su0 += __shfl_xor_sync(~0u, su0, 2);
        su1 += __shfl_xor_sync(~0u, su1, 1);
        su1 += __shfl_xor_sync(~0u, su1, 2);
        l0 = l0 * a0 + su0;
        l1 = l1 * a1 + su1;

        #pragma unroll
        for (int nf = 0; nf < 16; nf++) {
            o[nf][0] *= a0;
            o[nf][1] *= a0;
            o[nf][2] *= a1;
            o[nf][3] *= a1;
        }

        // ---- O += P V (split 3-product) ----
        #pragma unroll
        for (int c = 0; c < 2; c++) {
            #pragma unroll
            for (int nb = 0; nb < 8; nb++) {
                uint32_t vh4[4], vl4[4];
                unsigned off = (unsigned)((c * 16 + l15) * KST + nb * 16 + l16o) * 2u;
                ldsm_x4_t(vh4, svh_b + off);
                ldsm_x4_t(vl4, svl_b + off);
                uint32_t b0h[2], b1h[2], b0l[2], b1l[2];
                b0h[0] = vh4[0]; b0h[1] = vh4[1];
                b1h[0] = vh4[2]; b1h[1] = vh4[3];
                b0l[0] = vl4[0]; b0l[1] = vl4[1];
                b1l[0] = vl4[2]; b1l[1] = vl4[3];
                mma_bf16(o[2 * nb],     ph[c], b0h);
                mma_bf16(o[2 * nb],     pl[c], b0h);
                mma_bf16(o[2 * nb],     ph[c], b0l);
                mma_bf16(o[2 * nb + 1], ph[c], b1h);
                mma_bf16(o[2 * nb + 1], pl[c], b1h);
                mma_bf16(o[2 * nb + 1], ph[c], b1l);
            }
        }
        __syncthreads();
    }

    // ---- epilogue ----
    const float il0 = 1.0f / l0;
    const float il1 = 1.0f / l1;
    float* Y = g_Y + ((size_t)((b * NH + h) * T_SEQ + q0 + wm)) * DH;
    #pragma unroll
    for (int nf = 0; nf < 16; nf++) {
        *(float2*)(Y + (size_t)g * DH + nf * 8 + t2) =
            make_float2(o[nf][0] * il0, o[nf][1] * il0);
        *(float2*)(Y + (size_t)(g + 8) * DH + nf * 8 + t2) =
            make_float2(o[nf][2] * il1, o[nf][3] * il1);
    }
}

// ---------------- out = y * silu(g) ----------------
__global__ void final_kernel(float* __restrict__ out) {
    const int o = blockIdx.x * 256 + threadIdx.x;
    const float gv = g_gmat[o];
    const int d = o & 127;
    const int hh = (o >> 7) & 15;
    const int bt = o >> 11;
    const int t = bt & (T_SEQ - 1);
    const int b = bt >> 11;
    const float y = g_Y[(size_t)((b * NH + hh) * T_SEQ + t) * DH + d];
    out[o] = y * gv / (1.0f + expf(-gv));
}

// ---------------- launch ----------------
extern "C" void kernel_launch(void* const* d_in, const int* in_sizes, int n_in,
                              void* d_out, int out_size) {
    const float* x      = (const float*)d_in[0];
    const float* Wqkv   = (const float*)d_in[1];
    const float* Wrk    = (const float*)d_in[2];
    const float* brk    = (const float*)d_in[3];
    const float* scaler = (const float*)d_in[4];
    const float* Wg     = (const float*)d_in[5];
    float* out = (float*)d_out;

    float* p_qkv;
    float* p_g;
    __nv_bfloat16* p_Ah;
    __nv_bfloat16* p_Al;
    __nv_bfloat16* p_Bqh;
    __nv_bfloat16* p_Bql;
    __nv_bfloat16* p_Bgh;
    __nv_bfloat16* p_Bgl;
    cudaGetSymbolAddress((void**)&p_qkv, g_qkv);
    cudaGetSymbolAddress((void**)&p_g,   g_gmat);
    cudaGetSymbolAddress((void**)&p_Ah,  g_Ah);
    cudaGetSymbolAddress((void**)&p_Al,  g_Al);
    cudaGetSymbolAddress((void**)&p_Bqh, g_Bqh);
    cudaGetSymbolAddress((void**)&p_Bql, g_Bql);
    cudaGetSymbolAddress((void**)&p_Bgh, g_Bgh);
    cudaGetSymbolAddress((void**)&p_Bgl, g_Bgl);

    cvt_split<<<(BT * D_MODEL + 255) / 256, 256>>>(x, p_Ah, p_Al, BT * D_MODEL);
    cvt_split<<<(D_MODEL * QKV_N + 255) / 256, 256>>>(Wqkv, p_Bqh, p_Bql, D_MODEL * QKV_N);
    cvt_split<<<(D_MODEL * D_MODEL + 255) / 256, 256>>>(Wg, p_Bgh, p_Bgl, D_MODEL * D_MODEL);

    gemm_bf16x3<<<dim3(QKV_N / BN, BT / BM), 256>>>(p_Ah, p_Al, p_Bqh, p_Bql, p_qkv, QKV_N, D_MODEL);
    gemm_bf16x3<<<dim3(D_MODEL / BN, BT / BM), 256>>>(p_Ah, p_Al, p_Bgh, p_Bgl, p_g, D_MODEL, D_MODEL);

    rk_kernel<<<BT / 4, 256>>>(x, Wrk, brk);
    prep_kernel<<<BT, 256>>>(scaler);
    attn_kernel<<<dim3(T_SEQ / ATQ, NH, B_SZ), 256>>>();
    final_kernel<<<(BT * D_MODEL) / 256, 256>>>(out);
}

// round 8
// speedup vs baseline: 3.6029x; 1.0813x over previous
#include <cuda_runtime.h>
#include <cuda_bf16.h>
#include <stdint.h>
#include <math.h>

#define D_MODEL 2048
#define NH      16
#define NKV     4
#define DH      128
#define D1      64
#define D2      64
#define T_SEQ   2048
#define B_SZ    2
#define BT      (B_SZ * T_SEQ)          // 4096
#define WSIZE   1024
#define QKV_N   ((NH + NKV) * DH)       // 2560

// ---------------- scratch (device globals; no runtime allocation) ----------------
__device__ float g_qkv [BT * QKV_N];                 // raw x@W_qkv
__device__ float g_rkb [BT * D2];                    // raw x@W_rk + b
__device__ float g_gmat[BT * D_MODEL];               // raw x@W_g
__device__ float g_Y   [B_SZ * NH  * T_SEQ * DH];

// split-bf16 Q/K/V
__device__ __nv_bfloat16 g_Qh[B_SZ * NH  * T_SEQ * DH];
__device__ __nv_bfloat16 g_Ql[B_SZ * NH  * T_SEQ * DH];
__device__ __nv_bfloat16 g_Kh[B_SZ * NKV * T_SEQ * DH];
__device__ __nv_bfloat16 g_Kl[B_SZ * NKV * T_SEQ * DH];
__device__ __nv_bfloat16 g_Vh[B_SZ * NKV * T_SEQ * DH];
__device__ __nv_bfloat16 g_Vl[B_SZ * NKV * T_SEQ * DH];

// split-bf16 GEMM operand copies
__device__ __nv_bfloat16 g_Ah [BT * D_MODEL];
__device__ __nv_bfloat16 g_Al [BT * D_MODEL];
__device__ __nv_bfloat16 g_Bqh[D_MODEL * QKV_N];
__device__ __nv_bfloat16 g_Bql[D_MODEL * QKV_N];
__device__ __nv_bfloat16 g_Bgh[D_MODEL * D_MODEL];
__device__ __nv_bfloat16 g_Bgl[D_MODEL * D_MODEL];

// ---------------- fp32 -> (hi, lo) bf16 split ----------------
__global__ void cvt_split(const float* __restrict__ src, __nv_bfloat16* __restrict__ hi,
                          __nv_bfloat16* __restrict__ lo, int n) {
    int i = blockIdx.x * 256 + threadIdx.x;
    if (i < n) {
        float f = src[i];
        __nv_bfloat16 h = __float2bfloat16(f);
        hi[i] = h;
        lo[i] = __float2bfloat16(f - __bfloat162float(h));
    }
}

// ---------------- mma / ldmatrix / cp.async helpers ----------------
__device__ __forceinline__ void ldsm_x4(uint32_t* r, unsigned addr) {
    asm volatile("ldmatrix.sync.aligned.m8n8.x4.shared.b16 {%0,%1,%2,%3}, [%4];"
        : "=r"(r[0]), "=r"(r[1]), "=r"(r[2]), "=r"(r[3]) : "r"(addr));
}
__device__ __forceinline__ void ldsm_x4_t(uint32_t* r, unsigned addr) {
    asm volatile("ldmatrix.sync.aligned.m8n8.x4.trans.shared.b16 {%0,%1,%2,%3}, [%4];"
        : "=r"(r[0]), "=r"(r[1]), "=r"(r[2]), "=r"(r[3]) : "r"(addr));
}
__device__ __forceinline__ void mma_bf16(float* d, const uint32_t* a, const uint32_t* b) {
    asm volatile("mma.sync.aligned.m16n8k16.row.col.f32.bf16.bf16.f32 "
        "{%0,%1,%2,%3}, {%4,%5,%6,%7}, {%8,%9}, {%0,%1,%2,%3};"
        : "+f"(d[0]), "+f"(d[1]), "+f"(d[2]), "+f"(d[3])
        : "r"(a[0]), "r"(a[1]), "r"(a[2]), "r"(a[3]), "r"(b[0]), "r"(b[1]));
}
__device__ __forceinline__ uint32_t pack_bf16x2(float x, float y) {
    __nv_bfloat162 t = __floats2bfloat162_rn(x, y);
    return *(uint32_t*)&t;
}
__device__ __forceinline__ void cp16(unsigned saddr, const void* gptr) {
    asm volatile("cp.async.cg.shared.global [%0], [%1], 16;" :: "r"(saddr), "l"(gptr));
}
__device__ __forceinline__ void cp_commit() {
    asm volatile("cp.async.commit_group;");
}
__device__ __forceinline__ void cp_wait0() {
    asm volatile("cp.async.wait_group 0;");
}

// ---------------- merged tensor-core split-bf16 GEMM (double-buffered cp.async) ----------------
#define BM 128
#define BN 128
#define BK 32
#define AST 40
#define BST 136
#define NB1 (QKV_N / BN)     // 20 column-blocks for qkv
#define NB2 (D_MODEL / BN)   // 16 column-blocks for g
#define GA_OFF(buf, p) (((buf) * 2 + (p)) * BM * AST)
#define GB_OFF(buf, p) (4 * BM * AST + ((buf) * 2 + (p)) * BK * BST)
#define GSMEM_BYTES ((4 * BM * AST + 4 * BK * BST) * 2)

__device__ __forceinline__ void gemm_prefetch(
    unsigned sbase, int buf, int tid,
    const __nv_bfloat16* Ah, const __nv_bfloat16* Al,
    const __nv_bfloat16* Bh, const __nv_bfloat16* Bl,
    int m0, int n0, int kk0, int N, int K)
{
    const __nv_bfloat16* Ap[2];
    Ap[0] = Ah; Ap[1] = Al;
    const __nv_bfloat16* Bp[2];
    Bp[0] = Bh; Bp[1] = Bl;
    #pragma unroll
    for (int p = 0; p < 2; p++) {
        #pragma unroll
        for (int v = 0; v < 2; v++) {
            int vid = tid + v * 256;
            int ar = vid >> 2;
            int ac = (vid & 3) * 8;
            unsigned sa = sbase + (unsigned)(GA_OFF(buf, p) + ar * AST + ac) * 2u;
            cp16(sa, Ap[p] + (size_t)(m0 + ar) * K + kk0 + ac);
            int br = vid >> 4;
            int bc = (vid & 15) * 8;
            unsigned sb = sbase + (unsigned)(GB_OFF(buf, p) + br * BST + bc) * 2u;
            cp16(sb, Bp[p] + (size_t)(kk0 + br) * N + n0 + bc);
        }
    }
    cp_commit();
}

__global__ __launch_bounds__(256)
void gemm_bf16x3_dual(const __nv_bfloat16* __restrict__ Ah, const __nv_bfloat16* __restrict__ Al,
                      const __nv_bfloat16* __restrict__ B1h, const __nv_bfloat16* __restrict__ B1l,
                      float* __restrict__ C1,
                      const __nv_bfloat16* __restrict__ B2h, const __nv_bfloat16* __restrict__ B2l,
                      float* __restrict__ C2, int K) {
    extern __shared__ __nv_bfloat16 gsm[];
    const unsigned sbase = (unsigned)__cvta_generic_to_shared(gsm);

    const int tid  = threadIdx.x;
    const int lane = tid & 31;
    const int wid  = tid >> 5;
    const int m0 = blockIdx.y * BM;
    const int wm = (wid & 3) * 32;
    const int wn = (wid >> 2) * 64;

    const __nv_bfloat16* Bh;
    const __nv_bfloat16* Bl;
    float* C;
    int N;
    int n0;
    if (blockIdx.x < NB1) {
        Bh = B1h; Bl = B1l; C = C1; N = QKV_N; n0 = blockIdx.x * BN;
    } else {
        Bh = B2h; Bl = B2l; C = C2; N = D_MODEL; n0 = (blockIdx.x - NB1) * BN;
    }

    float acc[2][8][4];
    #pragma unroll
    for (int mf = 0; mf < 2; mf++) {
        #pragma unroll
        for (int nf = 0; nf < 8; nf++) {
            #pragma unroll
            for (int i = 0; i < 4; i++) { acc[mf][nf][i] = 0.f; }
        }
    }

    const int l15 = lane & 15;
    const int l16 = (lane >> 4) << 3;

    gemm_prefetch(sbase, 0, tid, Ah, Al, Bh, Bl, m0, n0, 0, N, K);

    int buf = 0;
    for (int k0 = 0; k0 < K; k0 += BK) {
        cp_wait0();
        __syncthreads();
        if (k0 + BK < K) {
            gemm_prefetch(sbase, buf ^ 1, tid, Ah, Al, Bh, Bl, m0, n0, k0 + BK, N, K);
        }

        const unsigned a_b0 = sbase + (unsigned)GA_OFF(buf, 0) * 2u;
        const unsigned a_b1 = sbase + (unsigned)GA_OFF(buf, 1) * 2u;
        const unsigned b_b0 = sbase + (unsigned)GB_OFF(buf, 0) * 2u;
        const unsigned b_b1 = sbase + (unsigned)GB_OFF(buf, 1) * 2u;

        #pragma unroll
        for (int kk = 0; kk < BK; kk += 16) {
            uint32_t afh[2][4];
            uint32_t afl[2][4];
            uint32_t bfh[8][2];
            uint32_t bfl[8][2];
            #pragma unroll
            for (int mf = 0; mf < 2; mf++) {
                unsigned off = (unsigned)((wm + mf * 16 + l15) * AST + kk + l16) * 2u;
                ldsm_x4(afh[mf], a_b0 + off);
                ldsm_x4(afl[mf], a_b1 + off);
            }
            #pragma unroll
            for (int nb = 0; nb < 4; nb++) {
                unsigned off = (unsigned)((kk + l15) * BST + wn + nb * 16 + l16) * 2u;
                uint32_t th[4];
                uint32_t tl[4];
                ldsm_x4_t(th, b_b0 + off);
                ldsm_x4_t(tl, b_b1 + off);
                bfh[2 * nb][0] = th[0]; bfh[2 * nb][1] = th[1];
                bfh[2 * nb + 1][0] = th[2]; bfh[2 * nb + 1][1] = th[3];
                bfl[2 * nb][0] = tl[0]; bfl[2 * nb][1] = tl[1];
                bfl[2 * nb + 1][0] = tl[2]; bfl[2 * nb + 1][1] = tl[3];
            }
            #pragma unroll
            for (int mf = 0; mf < 2; mf++) {
                #pragma unroll
                for (int nf = 0; nf < 8; nf++) {
                    mma_bf16(acc[mf][nf], afh[mf], bfh[nf]);
                    mma_bf16(acc[mf][nf], afl[mf], bfh[nf]);
                    mma_bf16(acc[mf][nf], afh[mf], bfl[nf]);
                }
            }
        }
        buf ^= 1;
    }

    const int grp = lane >> 2;
    const int t2  = (lane & 3) * 2;
    #pragma unroll
    for (int mf = 0; mf < 2; mf++) {
        #pragma unroll
        for (int nf = 0; nf < 8; nf++) {
            float* c0 = C + (size_t)(m0 + wm + mf * 16 + grp) * N + n0 + wn + nf * 8 + t2;
            *(float2*)c0 = make_float2(acc[mf][nf][0], acc[mf][nf][1]);
            float* c1 = c0 + (size_t)8 * N;
            *(float2*)c1 = make_float2(acc[mf][nf][2], acc[mf][nf][3]);
        }
    }
}

// ---------------- x @ W_rk + b_rk (N=64) ----------------
__global__ void rk_kernel(const float* __restrict__ X, const float* __restrict__ Wrk,
                          const float* __restrict__ brk) {
    const int tok0 = blockIdx.x << 2;
    __shared__ float xs[4][D_MODEL];
    for (int i = threadIdx.x; i < 4 * D_MODEL / 4; i += 256) {
        int tk = i >> 9;
        int cc = i & 511;
        ((float4*)xs[tk])[cc] = ((const float4*)(X + (size_t)(tok0 + tk) * D_MODEL))[cc];
    }
    __syncthreads();
    const int tk = threadIdx.x >> 6;
    const int n = threadIdx.x & 63;
    float acc = brk[n];
    for (int k = 0; k < D_MODEL; k++) { acc += xs[tk][k] * Wrk[k * 64 + n]; }
    g_rkb[(size_t)(tok0 + tk) * D2 + n] = acc;
}

// ---------------- rmsnorm + rope + scaling + KV scatter (bf16 split out) ----------------
__device__ __forceinline__ float inv_freq_f(int i) {
    return expf(-(float)i * 0.28782313662425575f);
}
__device__ __forceinline__ void store_split(__nv_bfloat16* hi, __nv_bfloat16* lo,
                                            size_t idx, float v) {
    __nv_bfloat16 h = __float2bfloat16(v);
    hi[idx] = h;
    lo[idx] = __float2bfloat16(v - __bfloat162float(h));
}

__global__ void prep_kernel(const float* __restrict__ scaler) {
    const int blk = blockIdx.x;
    const int b = blk / T_SEQ;
    const int t = blk % T_SEQ;
    const int w = threadIdx.x >> 5;
    const int lane = threadIdx.x & 31;
    __shared__ float sh[8][128];
    const float logpos = logf(fminf((float)(t + 1), 1024.0f));

    for (int h = w; h < NH + NKV; h += 8) {
        const float* row = g_qkv + (size_t)blk * QKV_N + h * 128;
        float v[4];
        float ss = 0.f;
        #pragma unroll
        for (int j = 0; j < 4; j++) { v[j] = row[(lane << 2) + j]; ss += v[j] * v[j]; }
        #pragma unroll
        for (int o = 16; o > 0; o >>= 1) { ss += __shfl_xor_sync(~0u, ss, o); }
        const float r = rsqrtf(ss * (1.0f / 128.0f) + 1e-6f);
        #pragma unroll
        for (int j = 0; j < 4; j++) { sh[w][(lane << 2) + j] = v[j] * r; }
        __syncwarp();

        if (h < NH) {
            const float sc = scaler[h] * logpos;
            size_t qbase = ((size_t)((b * NH + h) * T_SEQ + t)) * DH;
            #pragma unroll
            for (int j = 0; j < 4; j++) {
                int d = (lane << 2) + j;
                float outv;
                if (d < 64) {
                    outv = sh[w][d];
                } else {
                    int i = (d - 64) & 31;
                    float f = (float)t * inv_freq_f(i);
                    float c = cosf(f);
                    float s = sinf(f);
                    float x1 = sh[w][64 + i];
                    float x2 = sh[w][96 + i];
                    outv = (d < 96) ? (x1 * c + x2 * s) : (-x1 * s + x2 * c);
                }
                store_split(g_Qh, g_Ql, qbase + d, sc * outv);
            }
        } else {
            const int kvh = h - NH;
            size_t kvbase = ((size_t)((b * NKV + kvh) * T_SEQ + t)) * DH;
            #pragma unroll
            for (int j = 0; j < 4; j++) {
                int d = (lane << 2) + j;
                float val = sh[w][d];
                if (d < 64) {
                    store_split(g_Kh, g_Kl, kvbase + d, val);
                    store_split(g_Vh, g_Vl, kvbase + d, val);
                } else {
                    store_split(g_Vh, g_Vl, kvbase + d, val);
                }
            }
        }
        __syncwarp();
    }

    if (w == 0) {
        const float* rk = g_rkb + (size_t)blk * D2;
        float x1 = rk[lane];
        float x2 = rk[lane + 32];
        float f = (float)t * inv_freq_f(lane);
        float c = cosf(f);
        float s = sinf(f);
        float o1 = x1 * c + x2 * s;
        float o2 = -x1 * s + x2 * c;
        #pragma unroll
        for (int kvh = 0; kvh < NKV; kvh++) {
            size_t kvbase = ((size_t)((b * NKV + kvh) * T_SEQ + t)) * DH;
            store_split(g_Kh, g_Kl, kvbase + 64 + lane, o1);
            store_split(g_Kh, g_Kl, kvbase + 96 + lane, o2);
        }
    }
}

// ---------------- tensor-core windowed flash attention (double-buffered cp.async) ----------------
#define ATQ 128
#define ATK 32
#define KST 136
#define AOF(buf, a) (((buf) * 4 + (a)) * ATK * KST)
#define ASMEM_BYTES (8 * ATK * KST * 2)

__device__ __forceinline__ void attn_prefetch(
    unsigned sbase, int buf, int tid, int k0,
    const __nv_bfloat16* Khp, const __nv_bfloat16* Klp,
    const __nv_bfloat16* Vhp, const __nv_bfloat16* Vlp)
{
    #pragma unroll
    for (int v = 0; v < 2; v++) {
        int idx = tid + v * 256;
        int r = idx >> 4;
        int c = (idx & 15) << 3;
        size_t goff = (size_t)(k0 + r) * DH + c;
        unsigned soff = (unsigned)(r * KST + c) * 2u;
        cp16(sbase + (unsigned)AOF(buf, 0) * 2u + soff, Khp + goff);
        cp16(sbase + (unsigned)AOF(buf, 1) * 2u + soff, Klp + goff);
        cp16(sbase + (unsigned)AOF(buf, 2) * 2u + soff, Vhp + goff);
        cp16(sbase + (unsigned)AOF(buf, 3) * 2u + soff, Vlp + goff);
    }
    cp_commit();
}

__global__ __launch_bounds__(256) void attn_kernel() {
    extern __shared__ __nv_bfloat16 asmem[];
    const unsigned sbase = (unsigned)__cvta_generic_to_shared(asmem);

    const int q0  = blockIdx.x * ATQ;
    const int h   = blockIdx.y;
    const int b   = blockIdx.z;
    const int kvh = h >> 2;

    const int tid  = threadIdx.x;
    const int lane = tid & 31;
    const int wid  = tid >> 5;
    const int wm   = wid << 4;
    const int g    = lane >> 2;
    const int t2   = (lane & 3) << 1;
    const int l15  = lane & 15;
    const int l16o = (lane >> 4) << 3;

    // ---- Q fragments in registers (hi, lo), 8 k-chunks ----
    const __nv_bfloat16* Qhp = g_Qh + ((size_t)((b * NH + h) * T_SEQ + q0 + wm)) * DH;
    const __nv_bfloat16* Qlp = g_Ql + ((size_t)((b * NH + h) * T_SEQ + q0 + wm)) * DH;
    uint32_t qh[8][4];
    uint32_t ql[8][4];
    #pragma unroll
    for (int kk = 0; kk < 8; kk++) {
        int c0 = kk * 16 + t2;
        qh[kk][0] = *(const uint32_t*)(Qhp + (size_t)g * DH + c0);
        qh[kk][1] = *(const uint32_t*)(Qhp + (size_t)(g + 8) * DH + c0);
        qh[kk][2] = *(const uint32_t*)(Qhp + (size_t)g * DH + c0 + 8);
        qh[kk][3] = *(const uint32_t*)(Qhp + (size_t)(g + 8) * DH + c0 + 8);
        ql[kk][0] = *(const uint32_t*)(Qlp + (size_t)g * DH + c0);
        ql[kk][1] = *(const uint32_t*)(Qlp + (size_t)(g + 8) * DH + c0);
        ql[kk][2] = *(const uint32_t*)(Qlp + (size_t)g * DH + c0 + 8);
        ql[kk][3] = *(const uint32_t*)(Qlp + (size_t)(g + 8) * DH + c0 + 8);
    }

    const __nv_bfloat16* Khp = g_Kh + ((size_t)((b * NKV + kvh) * T_SEQ)) * DH;
    const __nv_bfloat16* Klp = g_Kl + ((size_t)((b * NKV + kvh) * T_SEQ)) * DH;
    const __nv_bfloat16* Vhp = g_Vh + ((size_t)((b * NKV + kvh) * T_SEQ)) * DH;
    const __nv_bfloat16* Vlp = g_Vl + ((size_t)((b * NKV + kvh) * T_SEQ)) * DH;

    float o[16][4];
    #pragma unroll
    for (int nf = 0; nf < 16; nf++) {
        #pragma unroll
        for (int i = 0; i < 4; i++) { o[nf][i] = 0.f; }
    }
    float m0 = -1e30f;
    float m1 = -1e30f;
    float l0 = 0.f;
    float l1 = 0.f;

    const int gi0 = q0 + wm + g;
    const int gi1 = gi0 + 8;
    const int kstart = (q0 >= WSIZE) ? (q0 - WSIZE) : 0;
    const float sscale = 0.08838834764831845f;   // 1/sqrt(128)

    attn_prefetch(sbase, 0, tid, kstart, Khp, Klp, Vhp, Vlp);

    int buf = 0;
    for (int k0 = kstart; k0 < q0 + ATQ; k0 += ATK) {
        cp_wait0();
        __syncthreads();
        if (k0 + ATK < q0 + ATQ) {
            attn_prefetch(sbase, buf ^ 1, tid, k0 + ATK, Khp, Klp, Vhp, Vlp);
        }

        const unsigned skh_b = sbase + (unsigned)AOF(buf, 0) * 2u;
        const unsigned skl_b = sbase + (unsigned)AOF(buf, 1) * 2u;
        const unsigned svh_b = sbase + (unsigned)AOF(buf, 2) * 2u;
        const unsigned svl_b = sbase + (unsigned)AOF(buf, 3) * 2u;

        // ---- S = Q K^T (split 3-product), S: m16 x n32 per warp ----
        float s[4][4];
        #pragma unroll
        for (int nb = 0; nb < 4; nb++) {
            #pragma unroll
            for (int i = 0; i < 4; i++) { s[nb][i] = 0.f; }
        }
        #pragma unroll
        for (int kk = 0; kk < 8; kk++) {
            uint32_t kh0[4], kh1[4], kl0[4], kl1[4];
            unsigned off0 = (unsigned)((l15) * KST + kk * 16 + l16o) * 2u;
            unsigned off1 = (unsigned)((16 + l15) * KST + kk * 16 + l16o) * 2u;
            ldsm_x4(kh0, skh_b + off0);
            ldsm_x4(kh1, skh_b + off1);
            ldsm_x4(kl0, skl_b + off0);
            ldsm_x4(kl1, skl_b + off1);
            uint32_t bh[4][2];
            uint32_t bl[4][2];
            bh[0][0] = kh0[0]; bh[0][1] = kh0[2];
            bh[1][0] = kh0[1]; bh[1][1] = kh0[3];
            bh[2][0] = kh1[0]; bh[2][1] = kh1[2];
            bh[3][0] = kh1[1]; bh[3][1] = kh1[3];
            bl[0][0] = kl0[0]; bl[0][1] = kl0[2];
            bl[1][0] = kl0[1]; bl[1][1] = kl0[3];
            bl[2][0] = kl1[0]; bl[2][1] = kl1[2];
            bl[3][0] = kl1[1]; bl[3][1] = kl1[3];
            #pragma unroll
            for (int nb = 0; nb < 4; nb++) {
                mma_bf16(s[nb], qh[kk], bh[nb]);
                mma_bf16(s[nb], ql[kk], bh[nb]);
                mma_bf16(s[nb], qh[kk], bl[nb]);
            }
        }

        // ---- mask + online softmax (rows g and g+8, warp-local) ----
        float mx0 = -1e30f;
        float mx1 = -1e30f;
        #pragma unroll
        for (int nb = 0; nb < 4; nb++) {
            #pragma unroll
            for (int ii = 0; ii < 2; ii++) {
                int j = k0 + nb * 8 + t2 + ii;
                float v0 = (j <= gi0 && j >= gi0 - WSIZE) ? s[nb][ii] * sscale : -1e30f;
                float v1 = (j <= gi1 && j >= gi1 - WSIZE) ? s[nb][2 + ii] * sscale : -1e30f;
                s[nb][ii] = v0;
                s[nb][2 + ii] = v1;
                mx0 = fmaxf(mx0, v0);
                mx1 = fmaxf(mx1, v1);
            }
        }
        mx0 = fmaxf(mx0, __shfl_xor_sync(~0u, mx0, 1));
        mx0 = fmaxf(mx0, __shfl_xor_sync(~0u, mx0, 2));
        mx1 = fmaxf(mx1, __shfl_xor_sync(~0u, mx1, 1));
        mx1 = fmaxf(mx1, __shfl_xor_sync(~0u, mx1, 2));
        float mn0 = fmaxf(m0, mx0);
        float mn1 = fmaxf(m1, mx1);
        float a0 = __expf(m0 - mn0);
        float a1 = __expf(m1 - mn1);
        m0 = mn0;
        m1 = mn1;

        float su0 = 0.f;
        float su1 = 0.f;
        uint32_t ph[2][4];
        uint32_t pl[2][4];
        #pragma unroll
        for (int nb = 0; nb < 4; nb++) {
            float p0 = __expf(s[nb][0] - mn0);
            float p1 = __expf(s[nb][1] - mn0);
            float p2 = __expf(s[nb][2] - mn1);
            float p3 = __expf(s[nb][3] - mn1);
            su0 += p0 + p1;
            su1 += p2 + p3;
            int c = nb >> 1;
            int half = (nb & 1) << 1;
            uint32_t h01 = pack_bf16x2(p0, p1);
            uint32_t h23 = pack_bf16x2(p2, p3);
            ph[c][half]     = h01;
            ph[c][half + 1] = h23;
            __nv_bfloat162* hp01 = (__nv_bfloat162*)&h01;
            __nv_bfloat162* hp23 = (__nv_bfloat162*)&h23;
            pl[c][half]     = pack_bf16x2(p0 - __bfloat162float(hp01->x),
                                          p1 - __bfloat162float(hp01->y));
            pl[c][half + 1] = pack_bf16x2(p2 - __bfloat162float(hp23->x),
                                          p3 - __bfloat162float(hp23->y));
        }
        su0 += __shfl_xor_sync(~0u, su0, 1);
        su0 += __shfl_xor_sync(~0u, su0, 2);
        su1 += __shfl_xor_sync(~0u, su1, 1);
        su1 += __shfl_xor_sync(~0u, su1, 2);
        l0 = l0 * a0 + su0;
        l1 = l1 * a1 + su1;

        #pragma unroll
        for (int nf = 0; nf < 16; nf++) {
            o[nf][0] *= a0;
            o[nf][1] *= a0;
            o[nf][2] *= a1;
            o[nf][3] *= a1;
        }

        // ---- O += P V (split 3-product) ----
        #pragma unroll
        for (int c = 0; c < 2; c++) {
            #pragma unroll
            for (int nb = 0; nb < 8; nb++) {
                uint32_t vh4[4], vl4[4];
                unsigned off = (unsigned)((c * 16 + l15) * KST + nb * 16 + l16o) * 2u;
                ldsm_x4_t(vh4, svh_b + off);
                ldsm_x4_t(vl4, svl_b + off);
                uint32_t b0h[2], b1h[2], b0l[2], b1l[2];
                b0h[0] = vh4[0]; b0h[1] = vh4[1];
                b1h[0] = vh4[2]; b1h[1] = vh4[3];
                b0l[0] = vl4[0]; b0l[1] = vl4[1];
                b1l[0] = vl4[2]; b1l[1] = vl4[3];
                mma_bf16(o[2 * nb],     ph[c], b0h);
                mma_bf16(o[2 * nb],     pl[c], b0h);
                mma_bf16(o[2 * nb],     ph[c], b0l);
                mma_bf16(o[2 * nb + 1], ph[c], b1h);
                mma_bf16(o[2 * nb + 1], pl[c], b1h);
                mma_bf16(o[2 * nb + 1], ph[c], b1l);
            }
        }
        buf ^= 1;
    }

    // ---- epilogue ----
    const float il0 = 1.0f / l0;
    const float il1 = 1.0f / l1;
    float* Y = g_Y + ((size_t)((b * NH + h) * T_SEQ + q0 + wm)) * DH;
    #pragma unroll
    for (int nf = 0; nf < 16; nf++) {
        *(float2*)(Y + (size_t)g * DH + nf * 8 + t2) =
            make_float2(o[nf][0] * il0, o[nf][1] * il0);
        *(float2*)(Y + (size_t)(g + 8) * DH + nf * 8 + t2) =
            make_float2(o[nf][2] * il1, o[nf][3] * il1);
    }
}

// ---------------- out = y * silu(g) ----------------
__global__ void final_kernel(float* __restrict__ out) {
    const int o = blockIdx.x * 256 + threadIdx.x;
    const float gv = g_gmat[o];
    const int d = o & 127;
    const int hh = (o >> 7) & 15;
    const int bt = o >> 11;
    const int t = bt & (T_SEQ - 1);
    const int b = bt >> 11;
    const float y = g_Y[(size_t)((b * NH + hh) * T_SEQ + t) * DH + d];
    out[o] = y * gv / (1.0f + expf(-gv));
}

// ---------------- launch ----------------
extern "C" void kernel_launch(void* const* d_in, const int* in_sizes, int n_in,
                              void* d_out, int out_size) {
    const float* x      = (const float*)d_in[0];
    const float* Wqkv   = (const float*)d_in[1];
    const float* Wrk    = (const float*)d_in[2];
    const float* brk    = (const float*)d_in[3];
    const float* scaler = (const float*)d_in[4];
    const float* Wg     = (const float*)d_in[5];
    float* out = (float*)d_out;

    float* p_qkv;
    float* p_g;
    __nv_bfloat16* p_Ah;
    __nv_bfloat16* p_Al;
    __nv_bfloat16* p_Bqh;
    __nv_bfloat16* p_Bql;
    __nv_bfloat16* p_Bgh;
    __nv_bfloat16* p_Bgl;
    cudaGetSymbolAddress((void**)&p_qkv, g_qkv);
    cudaGetSymbolAddress((void**)&p_g,   g_gmat);
    cudaGetSymbolAddress((void**)&p_Ah,  g_Ah);
    cudaGetSymbolAddress((void**)&p_Al,  g_Al);
    cudaGetSymbolAddress((void**)&p_Bqh, g_Bqh);
    cudaGetSymbolAddress((void**)&p_Bql, g_Bql);
    cudaGetSymbolAddress((void**)&p_Bgh, g_Bgh);
    cudaGetSymbolAddress((void**)&p_Bgl, g_Bgl);

    cudaFuncSetAttribute(gemm_bf16x3_dual,
                         cudaFuncAttributeMaxDynamicSharedMemorySize, GSMEM_BYTES);
    cudaFuncSetAttribute(attn_kernel,
                         cudaFuncAttributeMaxDynamicSharedMemorySize, ASMEM_BYTES);

    cvt_split<<<(BT * D_MODEL + 255) / 256, 256>>>(x, p_Ah, p_Al, BT * D_MODEL);
    cvt_split<<<(D_MODEL * QKV_N + 255) / 256, 256>>>(Wqkv, p_Bqh, p_Bql, D_MODEL * QKV_N);
    cvt_split<<<(D_MODEL * D_MODEL + 255) / 256, 256>>>(Wg, p_Bgh, p_Bgl, D_MODEL * D_MODEL);

    gemm_bf16x3_dual<<<dim3(NB1 + NB2, BT / BM), 256, GSMEM_BYTES>>>(
        p_Ah, p_Al, p_Bqh, p_Bql, p_qkv, p_Bgh, p_Bgl, p_g, D_MODEL);

    rk_kernel<<<BT / 4, 256>>>(x, Wrk, brk);
    prep_kernel<<<BT, 256>>>(scaler);
    attn_kernel<<<dim3(T_SEQ / ATQ, NH, B_SZ), 256, ASMEM_BYTES>>>();
    final_kernel<<<(BT * D_MODEL) / 256, 256>>>(out);
}